// round 4
// baseline (speedup 1.0000x reference)
#include <cuda_runtime.h>
#include <math.h>

#define NN      131072
#define DEG     16
#define NNZE    (NN*DEG)
#define GRID_F  296              // 2 CTAs/SM x 148 SMs: all co-resident (spin barrier safe)

typedef unsigned long long ull;

// ---- packed f32x2 helpers (Blackwell FFMA2; bit-identical fp32 math) ----
__device__ __forceinline__ ull ffma2(ull a, ull b, ull c) {
    ull d; asm("fma.rn.f32x2 %0, %1, %2, %3;" : "=l"(d) : "l"(a), "l"(b), "l"(c)); return d;
}
__device__ __forceinline__ ull fmul2(ull a, ull b) {
    ull d; asm("mul.rn.f32x2 %0, %1, %2;" : "=l"(d) : "l"(a), "l"(b)); return d;
}
__device__ __forceinline__ ull pack2(float x) {
    ull r; asm("mov.b64 %0, {%1, %1};" : "=l"(r) : "f"(x)); return r;
}
__device__ __forceinline__ float2 unpack2(ull a) {
    float lo, hi; asm("mov.b64 {%0, %1}, %2;" : "=f"(lo), "=f"(hi) : "l"(a));
    return make_float2(lo, hi);
}

// ---------------- scratch (static device globals; no allocation) ----------------
__device__ float  g_y [NN*32];
__device__ float  g_h1[NN*32];
__device__ float  g_h2[NN*64];
__device__ int    g_cnt[NN];
__device__ int    g_rowptr[NN+1];
__device__ int    g_cursor[NN];
__device__ float2 g_packed[NNZE];
__device__ unsigned g_barc[4];   // zero-init at module load; self-resetting
__device__ unsigned g_barg[4];

// ---- grid-wide barrier (all CTAs co-resident by construction) ----
__device__ __forceinline__ void gbar(int i) {
    __threadfence();             // each thread publishes its writes
    __syncthreads();
    if (threadIdx.x == 0) {
        unsigned gen = *(volatile unsigned*)&g_barg[i];
        unsigned prev = atomicAdd(&g_barc[i], 1);
        if (prev == gridDim.x - 1) {
            g_barc[i] = 0;
            __threadfence();
            atomicAdd(&g_barg[i], 1);
        } else {
            while (*(volatile unsigned*)&g_barg[i] == gen) { }
        }
    }
    __syncthreads();
}

// ---------------- fused: zero + x@W1, hist, scan, scatter ----------------
__global__ void __launch_bounds__(256, 2) k_fused(
    const float* __restrict__ x, const float* __restrict__ W1,
    const int* __restrict__ rows, const int* __restrict__ cols,
    const float* __restrict__ vals)
{
    __shared__ float sW[128*32];
    __shared__ int ss[256];
    int t = threadIdx.x;
    int gtid = blockIdx.x*256 + t;
    int gstride = GRID_F*256;

    for (int i = t; i < 1024; i += 256) ((float4*)sW)[i] = ((const float4*)W1)[i];
    __syncthreads();

    // phase 0: zero counts + y = x @ W1 (project 128->32 before SpMM)
    for (int i = gtid; i < NN; i += gstride) g_cnt[i] = 0;
    for (int row = gtid; row < NN; row += gstride) {
        const float4* xr = (const float4*)(x + (size_t)row*128);
        ull acc[16];
        #pragma unroll
        for (int j = 0; j < 16; j++) acc[j] = 0ull;
        #pragma unroll 4
        for (int k4 = 0; k4 < 32; k4++) {
            float4 xv = xr[k4];
            #pragma unroll
            for (int c = 0; c < 4; c++) {
                float xk = (c==0) ? xv.x : (c==1) ? xv.y : (c==2) ? xv.z : xv.w;
                ull xp = pack2(xk);
                const ulonglong2* wr = (const ulonglong2*)(sW + (k4*4+c)*32);
                #pragma unroll
                for (int j = 0; j < 8; j++) {
                    ulonglong2 w = wr[j];
                    acc[2*j+0] = ffma2(xp, w.x, acc[2*j+0]);
                    acc[2*j+1] = ffma2(xp, w.y, acc[2*j+1]);
                }
            }
        }
        ulonglong2* yo = (ulonglong2*)(g_y + (size_t)row*32);
        #pragma unroll
        for (int j = 0; j < 8; j++) {
            ulonglong2 u; u.x = acc[2*j]; u.y = acc[2*j+1];
            yo[j] = u;
        }
    }
    gbar(0);

    // phase 1: histogram of row ids
    #pragma unroll 4
    for (int e = gtid; e < NNZE; e += gstride) atomicAdd(&g_cnt[rows[e]], 1);
    gbar(1);

    // phase 2: exclusive scan (block 0; __ldcg avoids stale L1 from phase-0 stores)
    if (blockIdx.x == 0) {
        int base = t * 512;
        int s = 0;
        for (int i = 0; i < 512; i++) s += __ldcg(&g_cnt[base+i]);
        ss[t] = s;
        __syncthreads();
        for (int off = 1; off < 256; off <<= 1) {
            int v = (t >= off) ? ss[t-off] : 0;
            __syncthreads();
            ss[t] += v;
            __syncthreads();
        }
        int run = (t == 0) ? 0 : ss[t-1];
        for (int i = 0; i < 512; i++) {
            int c = __ldcg(&g_cnt[base+i]);
            g_rowptr[base+i] = run;
            g_cursor[base+i] = run;
            run += c;
        }
        if (t == 255) g_rowptr[NN] = run;
    }
    gbar(2);

    // phase 3: scatter edges into row-grouped layout
    #pragma unroll 4
    for (int e = gtid; e < NNZE; e += gstride) {
        int r = rows[e];
        int pos = atomicAdd(&g_cursor[r], 1);
        g_packed[pos] = make_float2(__int_as_float(cols[e]), vals[e]);
    }
}

// ---------------- SpMM 1: h1 = relu(spmm(y) + b1)  (warp per row) ----------------
__global__ void __launch_bounds__(256) k_spmm1(const float* __restrict__ b1) {
    int w = (blockIdx.x*256 + threadIdx.x) >> 5;
    int lane = threadIdx.x & 31;
    int s = g_rowptr[w], e = g_rowptr[w+1];
    float acc = 0.f;
    for (int i = s; i < e; i++) {
        float2 p = g_packed[i];
        acc += p.y * g_y[__float_as_int(p.x)*32 + lane];
    }
    g_h1[w*32 + lane] = fmaxf(acc + b1[lane], 0.f);
}

// ---------------- SpMM 2 fused with @W2: h2 = relu(spmm(h1)@W2 + b2) -------------
__global__ void __launch_bounds__(256) k_spmm2(const float* __restrict__ W2,
                                               const float* __restrict__ b2) {
    __shared__ float sW[32*64];
    __shared__ float sz[8][33];
    int t = threadIdx.x;
    for (int i = t; i < 512; i += 256) ((float4*)sW)[i] = ((const float4*)W2)[i];
    __syncthreads();
    int w = (blockIdx.x*256 + t) >> 5;
    int wl = t >> 5, lane = t & 31;
    int s = g_rowptr[w], e = g_rowptr[w+1];
    float acc = 0.f;
    for (int i = s; i < e; i++) {
        float2 p = g_packed[i];
        acc += p.y * g_h1[__float_as_int(p.x)*32 + lane];
    }
    sz[wl][lane] = acc;
    __syncwarp();
    float o0 = b2[lane], o1 = b2[lane+32];
    #pragma unroll
    for (int k = 0; k < 32; k++) {
        float zv = sz[wl][k];
        o0 += zv * sW[k*64 + lane];
        o1 += zv * sW[k*64 + lane + 32];
    }
    size_t off = (size_t)w * 64;
    g_h2[off + lane]      = fmaxf(o0, 0.f);
    g_h2[off + lane + 32] = fmaxf(o1, 0.f);
}

// ---------------- fused transformer block + classifier + log_softmax -------------
#define SW_FLOATS   12288
#define KV_STRIDE   68
#define SH_STRIDE   133
#define SMEM_FLOATS (SW_FLOATS + 2*256*KV_STRIDE)
#define SMEM_BYTES  (SMEM_FLOATS*4)

__device__ __forceinline__ void gemm64p(const float* xin,
                                        const float* __restrict__ sw, int ws,
                                        int coff, ull (&acc)[16]) {
    #pragma unroll
    for (int k = 0; k < 64; k++) {
        ull xp = pack2(xin[k]);
        const ulonglong2* wr = (const ulonglong2*)(sw + k*ws + coff);
        #pragma unroll
        for (int j = 0; j < 8; j++) {
            ulonglong2 w = wr[j];
            acc[2*j+0] = ffma2(xp, w.x, acc[2*j+0]);
            acc[2*j+1] = ffma2(xp, w.y, acc[2*j+1]);
        }
    }
}

__device__ __forceinline__ void layernorm64(float (&v)[64], const float* __restrict__ g,
                                            const float* __restrict__ b) {
    float mu = 0.f;
    #pragma unroll
    for (int j = 0; j < 64; j++) mu += v[j];
    mu *= (1.f/64.f);
    float var = 0.f;
    #pragma unroll
    for (int j = 0; j < 64; j++) { float d = v[j]-mu; var += d*d; }
    var *= (1.f/64.f);
    float inv = rsqrtf(var + 1e-5f);
    #pragma unroll
    for (int j = 0; j < 64; j++) v[j] = (v[j]-mu)*inv*g[j] + b[j];
}

__global__ void __launch_bounds__(256) k_tr(
    const float* __restrict__ Wqkv, const float* __restrict__ bqkv,
    const float* __restrict__ Wo,   const float* __restrict__ bo,
    const float* __restrict__ g1,   const float* __restrict__ be1,
    const float* __restrict__ Wf1,  const float* __restrict__ bf1,
    const float* __restrict__ Wf2,  const float* __restrict__ bf2,
    const float* __restrict__ g2,   const float* __restrict__ be2,
    const float* __restrict__ Wc,   const float* __restrict__ bc,
    float* __restrict__ out)
{
    extern __shared__ float sm[];
    float* sw = sm;                              // 12288-float weight scratch
    float* sK = sm + SW_FLOATS;                  // 256 x 68
    float* sV = sK + 256*KV_STRIDE;              // 256 x 68
    float* sH = sm + SW_FLOATS;                  // 256 x 133, reuses K/V post-attention
    int t = threadIdx.x;
    int blk = blockIdx.x;
    const float4* xr4 = (const float4*)(g_h2 + ((size_t)blk*256 + t)*64);

    // ---- stage W_qkv (64x192) ----
    for (int i = t; i < 3072; i += 256) ((float4*)sw)[i] = ((const float4*)Wqkv)[i];
    __syncthreads();

    // ---- phase 1: qkv projection; q packed in regs, K/V -> smem ----
    ull q2[32];
    #pragma unroll
    for (int ch = 0; ch < 6; ch++) {
        ull acc[16];
        const ull* bp = (const ull*)(bqkv + ch*32);
        #pragma unroll
        for (int j = 0; j < 16; j++) acc[j] = bp[j];
        #pragma unroll
        for (int k4 = 0; k4 < 16; k4++) {
            float4 xv = xr4[k4];
            #pragma unroll
            for (int c = 0; c < 4; c++) {
                float xk = (c==0) ? xv.x : (c==1) ? xv.y : (c==2) ? xv.z : xv.w;
                ull xp = pack2(xk);
                const ulonglong2* wr = (const ulonglong2*)(sw + (k4*4+c)*192 + ch*32);
                #pragma unroll
                for (int j = 0; j < 8; j++) {
                    ulonglong2 w = wr[j];
                    acc[2*j+0] = ffma2(xp, w.x, acc[2*j+0]);
                    acc[2*j+1] = ffma2(xp, w.y, acc[2*j+1]);
                }
            }
        }
        if (ch < 2) {
            #pragma unroll
            for (int j = 0; j < 16; j++) q2[ch*16 + j] = acc[j];
        } else {
            float* dst = (ch < 4) ? (sK + t*KV_STRIDE + (ch-2)*32)
                                  : (sV + t*KV_STRIDE + (ch-4)*32);
            #pragma unroll
            for (int j = 0; j < 8; j++) {
                ulonglong2 u; u.x = acc[2*j]; u.y = acc[2*j+1];
                ((ulonglong2*)dst)[j] = u;
            }
        }
    }
    __syncthreads();

    // stage W_o early (disjoint from K/V); post-attention barrier covers visibility
    for (int i = t; i < 1024; i += 256) ((float4*)sw)[i] = ((const float4*)Wo)[i];

    // ---- pass 1: per-head running max, ALL 4 heads fused per key (8 indep chains) ----
    float mh0 = -1e30f, mh1 = -1e30f, mh2 = -1e30f, mh3 = -1e30f;
    for (int kk = 0; kk < 256; kk++) {
        const ulonglong2* kp = (const ulonglong2*)(sK + kk*KV_STRIDE);
        #pragma unroll
        for (int h = 0; h < 4; h++) {
            ulonglong2 k0 = kp[h*4+0], k1 = kp[h*4+1], k2 = kp[h*4+2], k3 = kp[h*4+3];
            ull sa = fmul2(q2[h*8+0], k0.x);
            ull sb = fmul2(q2[h*8+2], k1.x);
            sa = ffma2(q2[h*8+1], k0.y, sa);
            sb = ffma2(q2[h*8+3], k1.y, sb);
            sa = ffma2(q2[h*8+4], k2.x, sa);
            sb = ffma2(q2[h*8+5], k2.y, sb);
            sa = ffma2(q2[h*8+6], k3.x, sa);
            sb = ffma2(q2[h*8+7], k3.y, sb);
            float2 u = unpack2(sa), v = unpack2(sb);
            float s = (u.x + u.y) + (v.x + v.y);
            if (h == 0) mh0 = fmaxf(mh0, s);
            else if (h == 1) mh1 = fmaxf(mh1, s);
            else if (h == 2) mh2 = fmaxf(mh2, s);
            else mh3 = fmaxf(mh3, s);
        }
    }

    // ---- pass 2: softmax + ctx, head-pairs fused (4 score chains, 16 ctx chains) ----
    float o[64];
    #pragma unroll
    for (int hp = 0; hp < 2; hp++) {
        const int b = hp*16;
        float m0 = (hp == 0) ? mh0 : mh2;
        float m1 = (hp == 0) ? mh1 : mh3;
        float l0 = 0.f, l1 = 0.f;
        ull c[16];
        #pragma unroll
        for (int j = 0; j < 16; j++) c[j] = 0ull;
        for (int kk = 0; kk < 256; kk++) {
            const ulonglong2* kp = (const ulonglong2*)(sK + kk*KV_STRIDE + hp*32);
            ulonglong2 k0=kp[0], k1=kp[1], k2=kp[2], k3=kp[3];
            ulonglong2 k4=kp[4], k5=kp[5], k6=kp[6], k7=kp[7];
            ull sa = fmul2(q2[b+0],  k0.x);
            ull sb = fmul2(q2[b+2],  k1.x);
            ull ta = fmul2(q2[b+8],  k4.x);
            ull tb = fmul2(q2[b+10], k5.x);
            sa = ffma2(q2[b+1],  k0.y, sa);
            sb = ffma2(q2[b+3],  k1.y, sb);
            ta = ffma2(q2[b+9],  k4.y, ta);
            tb = ffma2(q2[b+11], k5.y, tb);
            sa = ffma2(q2[b+4],  k2.x, sa);
            sb = ffma2(q2[b+5],  k2.y, sb);
            ta = ffma2(q2[b+12], k6.x, ta);
            tb = ffma2(q2[b+13], k6.y, tb);
            sa = ffma2(q2[b+6],  k3.x, sa);
            sb = ffma2(q2[b+7],  k3.y, sb);
            ta = ffma2(q2[b+14], k7.x, ta);
            tb = ffma2(q2[b+15], k7.y, tb);
            float2 u = unpack2(sa), v = unpack2(sb);
            float2 w = unpack2(ta), z = unpack2(tb);
            float p0 = __expf((((u.x+u.y)+(v.x+v.y)) - m0) * 0.25f);
            float p1 = __expf((((w.x+w.y)+(z.x+z.y)) - m1) * 0.25f);
            l0 += p0; l1 += p1;
            ull pp0 = pack2(p0), pp1 = pack2(p1);
            const ulonglong2* vp = (const ulonglong2*)(sV + kk*KV_STRIDE + hp*32);
            ulonglong2 v0=vp[0], v1=vp[1], v2=vp[2], v3=vp[3];
            ulonglong2 v4=vp[4], v5=vp[5], v6=vp[6], v7=vp[7];
            c[0]  = ffma2(pp0, v0.x, c[0]);  c[1]  = ffma2(pp0, v0.y, c[1]);
            c[2]  = ffma2(pp0, v1.x, c[2]);  c[3]  = ffma2(pp0, v1.y, c[3]);
            c[4]  = ffma2(pp0, v2.x, c[4]);  c[5]  = ffma2(pp0, v2.y, c[5]);
            c[6]  = ffma2(pp0, v3.x, c[6]);  c[7]  = ffma2(pp0, v3.y, c[7]);
            c[8]  = ffma2(pp1, v4.x, c[8]);  c[9]  = ffma2(pp1, v4.y, c[9]);
            c[10] = ffma2(pp1, v5.x, c[10]); c[11] = ffma2(pp1, v5.y, c[11]);
            c[12] = ffma2(pp1, v6.x, c[12]); c[13] = ffma2(pp1, v6.y, c[13]);
            c[14] = ffma2(pp1, v7.x, c[14]); c[15] = ffma2(pp1, v7.y, c[15]);
        }
        ull i0 = pack2(1.f / l0), i1 = pack2(1.f / l1);
        #pragma unroll
        for (int j = 0; j < 8; j++) {
            float2 r0 = unpack2(fmul2(c[j], i0));
            o[hp*32 + 2*j + 0] = r0.x;
            o[hp*32 + 2*j + 1] = r0.y;
            float2 r1 = unpack2(fmul2(c[8+j], i1));
            o[hp*32 + 16 + 2*j + 0] = r1.x;
            o[hp*32 + 16 + 2*j + 1] = r1.y;
        }
    }
    __syncthreads();   // W_o visible; everyone done with K/V

    // ---- a = o @ W_o + b_o;  x1 = LN1(x + a) ----
    float x1[64];
    #pragma unroll
    for (int ch = 0; ch < 2; ch++) {
        ull acc[16];
        const ull* bp = (const ull*)(bo + ch*32);
        #pragma unroll
        for (int j = 0; j < 16; j++) acc[j] = bp[j];
        gemm64p(o, sw, 64, ch*32, acc);
        #pragma unroll
        for (int j = 0; j < 16; j++) {
            float2 v = unpack2(acc[j]);
            x1[ch*32 + 2*j + 0] = v.x;
            x1[ch*32 + 2*j + 1] = v.y;
        }
    }
    #pragma unroll
    for (int k4 = 0; k4 < 16; k4++) {
        float4 xv = xr4[k4];
        x1[4*k4+0] += xv.x; x1[4*k4+1] += xv.y; x1[4*k4+2] += xv.z; x1[4*k4+3] += xv.w;
    }
    layernorm64(x1, g1, be1);
    __syncthreads();

    // ---- FFN up: h = gelu(x1 @ W_ff1 + b_ff1) -> own smem row ----
    for (int i = t; i < 2048; i += 256) ((float4*)sw)[i] = ((const float4*)Wf1)[i];
    __syncthreads();
    float* hrow = sH + t*SH_STRIDE;
    #pragma unroll
    for (int ch = 0; ch < 4; ch++) {
        ull acc[16];
        const ull* bp = (const ull*)(bf1 + ch*32);
        #pragma unroll
        for (int j = 0; j < 16; j++) acc[j] = bp[j];
        gemm64p(x1, sw, 128, ch*32, acc);
        #pragma unroll
        for (int j = 0; j < 16; j++) {
            float2 v = unpack2(acc[j]);
            hrow[ch*32 + 2*j + 0] = 0.5f*v.x*(1.f + erff(v.x*0.70710678118654752f));
            hrow[ch*32 + 2*j + 1] = 0.5f*v.y*(1.f + erff(v.y*0.70710678118654752f));
        }
    }
    __syncthreads();

    // ---- FFN down + residual + LN2 ----
    for (int i = t; i < 2048; i += 256) ((float4*)sw)[i] = ((const float4*)Wf2)[i];
    __syncthreads();
    float x2[64];
    #pragma unroll
    for (int ch = 0; ch < 2; ch++) {
        ull acc[16];
        const ull* bp = (const ull*)(bf2 + ch*32);
        #pragma unroll
        for (int j = 0; j < 16; j++) acc[j] = bp[j];
        #pragma unroll 4
        for (int k = 0; k < 128; k++) {
            ull hp = pack2(hrow[k]);
            const ulonglong2* wr = (const ulonglong2*)(sw + k*64 + ch*32);
            #pragma unroll
            for (int j = 0; j < 8; j++) {
                ulonglong2 w = wr[j];
                acc[2*j+0] = ffma2(hp, w.x, acc[2*j+0]);
                acc[2*j+1] = ffma2(hp, w.y, acc[2*j+1]);
            }
        }
        #pragma unroll
        for (int j = 0; j < 16; j++) {
            float2 v = unpack2(acc[j]);
            x2[ch*32 + 2*j + 0] = v.x + x1[ch*32 + 2*j + 0];
            x2[ch*32 + 2*j + 1] = v.y + x1[ch*32 + 2*j + 1];
        }
    }
    layernorm64(x2, g2, be2);
    __syncthreads();

    // ---- classifier + log_softmax ----
    for (int i = t; i < 256; i += 256) ((float4*)sw)[i] = ((const float4*)Wc)[i];
    __syncthreads();
    ull lg2[8];
    const ull* bcp = (const ull*)bc;
    #pragma unroll
    for (int j = 0; j < 8; j++) lg2[j] = bcp[j];
    #pragma unroll
    for (int k = 0; k < 64; k++) {
        ull xp = pack2(x2[k]);
        const ulonglong2* wr = (const ulonglong2*)(sw + k*16);
        #pragma unroll
        for (int j = 0; j < 4; j++) {
            ulonglong2 w = wr[j];
            lg2[2*j+0] = ffma2(xp, w.x, lg2[2*j+0]);
            lg2[2*j+1] = ffma2(xp, w.y, lg2[2*j+1]);
        }
    }
    float lg[16];
    #pragma unroll
    for (int j = 0; j < 8; j++) {
        float2 v = unpack2(lg2[j]);
        lg[2*j] = v.x; lg[2*j+1] = v.y;
    }
    float mm = lg[0];
    #pragma unroll
    for (int j = 1; j < 16; j++) mm = fmaxf(mm, lg[j]);
    float ssum = 0.f;
    #pragma unroll
    for (int j = 0; j < 16; j++) ssum += __expf(lg[j] - mm);
    float lse = mm + logf(ssum);
    float4* op = (float4*)(out + ((size_t)blk*256 + t)*16);
    #pragma unroll
    for (int j4 = 0; j4 < 4; j4++)
        op[j4] = make_float4(lg[4*j4]-lse, lg[4*j4+1]-lse, lg[4*j4+2]-lse, lg[4*j4+3]-lse);
}

// ---------------- launch ----------------
extern "C" void kernel_launch(void* const* d_in, const int* in_sizes, int n_in,
                              void* d_out, int out_size) {
    const float* x    = (const float*)d_in[0];
    const int*   rows = (const int*)  d_in[1];
    const int*   cols = (const int*)  d_in[2];
    const float* vals = (const float*)d_in[3];
    const float* W1   = (const float*)d_in[4];
    const float* b1   = (const float*)d_in[5];
    const float* W2   = (const float*)d_in[6];
    const float* b2   = (const float*)d_in[7];
    const float* Wqkv = (const float*)d_in[8];
    const float* bqkv = (const float*)d_in[9];
    const float* Wo   = (const float*)d_in[10];
    const float* bo   = (const float*)d_in[11];
    const float* g1   = (const float*)d_in[12];
    const float* be1  = (const float*)d_in[13];
    const float* Wf1  = (const float*)d_in[14];
    const float* bf1  = (const float*)d_in[15];
    const float* Wf2  = (const float*)d_in[16];
    const float* bf2  = (const float*)d_in[17];
    const float* g2   = (const float*)d_in[18];
    const float* be2  = (const float*)d_in[19];
    const float* Wc   = (const float*)d_in[20];
    const float* bc   = (const float*)d_in[21];
    float* out = (float*)d_out;

    static bool attr_set = false;
    if (!attr_set) {
        cudaFuncSetAttribute(k_tr, cudaFuncAttributeMaxDynamicSharedMemorySize, SMEM_BYTES);
        attr_set = true;
    }

    k_fused <<<GRID_F, 256>>>(x, W1, rows, cols, vals);
    k_spmm1 <<<NN/8, 256>>>(b1);
    k_spmm2 <<<NN/8, 256>>>(W2, b2);
    k_tr    <<<NN/256, 256, SMEM_BYTES>>>(Wqkv, bqkv, Wo, bo, g1, be1,
                                          Wf1, bf1, Wf2, bf2, g2, be2,
                                          Wc, bc, out);
}